// round 14
// baseline (speedup 1.0000x reference)
#include <cuda_runtime.h>
#include <math.h>
#include <stdint.h>

#define BB 8
#define NN 8192
#define MM 1024
#define KK 64
#define NG 8
#define BM (BB * MM)
#define NWORK 140

// ---------------- scratch (device globals; no allocations allowed) ----------------
__device__ float g_ft[(size_t)BB * NN * 64];     // features transposed [b][n][c]
__device__ float g_tt[(size_t)BB * NN * 64];     // temb transposed [b][n][c]
__device__ int   g_cidx[BB * MM];                // fps indices
__device__ float g_y1[(size_t)BB * MM * KK * 64];   // layer1 pre-norm  [bm][k][c]
__device__ float g_mnmx[(size_t)128 * BM * 2];   // per (c, bm): min,max of y2 over k
__device__ float g_part1[16 * BM];               // [2g+slot][bm] partial (sum,sumsq)
__device__ float g_part2[16 * BM];
__device__ float g_aff1[BB * 64 * 2];            // per (b,c): scale, shift
__device__ float g_aff2[BB * 128 * 2];
__device__ int   g_prog[BB * 32];                // fps progress per batch (128B padded)

__device__ __forceinline__ float sqdist3(float dx, float dy, float dz) {
    return __fadd_rn(__fadd_rn(__fmul_rn(dx, dx), __fmul_rn(dy, dy)), __fmul_rn(dz, dz));
}

// ---------------- packed f32x2 helpers ----------------
__device__ __forceinline__ unsigned long long pk2(float lo, float hi) {
    unsigned long long r;
    asm("mov.b64 %0, {%1, %2};" : "=l"(r) : "f"(lo), "f"(hi));
    return r;
}
__device__ __forceinline__ unsigned long long ffma2(unsigned long long a,
                                                    unsigned long long b,
                                                    unsigned long long c) {
    unsigned long long d;
    asm("fma.rn.f32x2 %0, %1, %2, %3;" : "=l"(d) : "l"(a), "l"(b), "l"(c));
    return d;
}
__device__ __forceinline__ unsigned long long add2(unsigned long long a, unsigned long long b) {
    unsigned long long d;
    asm("add.rn.f32x2 %0, %1, %2;" : "=l"(d) : "l"(a), "l"(b));
    return d;
}
__device__ __forceinline__ unsigned long long mul2(unsigned long long a, unsigned long long b) {
    unsigned long long d;
    asm("mul.rn.f32x2 %0, %1, %2;" : "=l"(d) : "l"(a), "l"(b));
    return d;
}
__device__ __forceinline__ void upk2(unsigned long long v, float& lo, float& hi) {
    asm("mov.b64 {%0, %1}, %2;" : "=f"(lo), "=f"(hi) : "l"(v));
}

// ---------------- init: reset progress flags ----------------
__global__ void init_kernel() {
    if (threadIdx.x < BB) g_prog[threadIdx.x * 32] = -1;
}

// ---------------- transpose [b][c][n] -> [b][n][c] (c = 64) ----------------
__global__ void transpose_kernel(const float* __restrict__ in, int which) {
    __shared__ float tile[32][33];
    float* out = which ? g_tt : g_ft;
    int b = blockIdx.z;
    int c0 = blockIdx.y * 32;
    int n0 = blockIdx.x * 32;
    int tx = threadIdx.x, ty = threadIdx.y;
    const float* inb = in + (size_t)b * 64 * NN;
    float* outb = out + (size_t)b * NN * 64;
    #pragma unroll
    for (int i = 0; i < 32; i += 8)
        tile[ty + i][tx] = inb[(size_t)(c0 + ty + i) * NN + n0 + tx];
    __syncthreads();
    #pragma unroll
    for (int i = 0; i < 32; i += 8)
        outb[(size_t)(n0 + ty + i) * 64 + c0 + tx] = tile[tx][ty + i];
}

// ---------------- fused: blocks 0-7 = FPS producer; blocks 8-147 = workers ----------------
// Worker static smem (unused by fps blocks)
__global__ void __launch_bounds__(512, 1)
fused_kernel(const float* __restrict__ coords,
             const float* __restrict__ w1, const float* __restrict__ b1,
             float* __restrict__ out_centers, float* __restrict__ out_temb) {
    extern __shared__ float fsm[];               // fps: sx/sy/sz (96KB)
    __shared__ unsigned swv[16], swi[16];
    __shared__ float sctr[3];
    // worker arrays
    __shared__ __align__(16) unsigned long long w1p[32 * 68];  // 17408 B
    __shared__ float nf[68 * 65];                               // 17680 B
    __shared__ float b1s[64];
    __shared__ int s_i[16][KK];                                 // 4096 B
    __shared__ float pred[512 * 2];                             // 4096 B

    int t = threadIdx.x;
    int lane = t & 31, warp = t >> 5;

    if (blockIdx.x < BB) {
        // ================= FPS (identical to R13 512-thread version) =================
        float* sx = fsm;
        float* sy = fsm + NN;
        float* sz = fsm + 2 * NN;
        int b = blockIdx.x;
        const float* cb = coords + (size_t)b * 3 * NN;

        int base = t * 16;
        unsigned long long X2[8], Y2[8], Z2[8];
        #pragma unroll
        for (int q = 0; q < 4; q++) {
            float4 vx = *reinterpret_cast<const float4*>(cb + base + q * 4);
            float4 vy = *reinterpret_cast<const float4*>(cb + NN + base + q * 4);
            float4 vz = *reinterpret_cast<const float4*>(cb + 2 * NN + base + q * 4);
            X2[2 * q] = pk2(vx.x, vx.y); X2[2 * q + 1] = pk2(vx.z, vx.w);
            Y2[2 * q] = pk2(vy.x, vy.y); Y2[2 * q + 1] = pk2(vy.z, vy.w);
            Z2[2 * q] = pk2(vz.x, vz.y); Z2[2 * q + 1] = pk2(vz.z, vz.w);
            *reinterpret_cast<float4*>(sx + base + q * 4) = vx;
            *reinterpret_cast<float4*>(sy + base + q * 4) = vy;
            *reinterpret_cast<float4*>(sz + base + q * 4) = vz;
        }
        float D[16];
        #pragma unroll
        for (int i = 0; i < 16; i++) D[i] = 1e10f;

        float px = cb[0], py = cb[NN], pz = cb[2 * NN];
        if (t == 0) {
            g_cidx[b * MM] = 0;
            out_centers[(size_t)(b * 3 + 0) * MM] = px;
            out_centers[(size_t)(b * 3 + 1) * MM] = py;
            out_centers[(size_t)(b * 3 + 2) * MM] = pz;
            asm volatile("st.release.gpu.b32 [%0], %1;"
                         :: "l"(&g_prog[b * 32]), "r"(0) : "memory");
        }
        __syncthreads();

        for (int it = 1; it < MM; it++) {
            unsigned long long nx2 = pk2(-px, -px);
            unsigned long long ny2 = pk2(-py, -py);
            unsigned long long nz2 = pk2(-pz, -pz);
            unsigned bv = 0u;
            unsigned bi = (unsigned)base;
            #pragma unroll
            for (int p = 0; p < 8; p++) {
                unsigned long long dx = add2(X2[p], nx2);
                unsigned long long dy = add2(Y2[p], ny2);
                unsigned long long dz = add2(Z2[p], nz2);
                unsigned long long s = ffma2(dx, dx, ffma2(dy, dy, mul2(dz, dz)));
                float lo, hi;
                upk2(s, lo, hi);
                float n0 = fminf(D[2 * p], lo);
                float n1 = fminf(D[2 * p + 1], hi);
                D[2 * p] = n0;
                D[2 * p + 1] = n1;
                unsigned u0 = __float_as_uint(n0);
                unsigned u1 = __float_as_uint(n1);
                if (u0 > bv) { bv = u0; bi = (unsigned)(base + 2 * p); }
                if (u1 > bv) { bv = u1; bi = (unsigned)(base + 2 * p + 1); }
            }
            unsigned wmax = __reduce_max_sync(0xffffffffu, bv);
            unsigned cnd = (bv == wmax) ? bi : 0xffffffffu;
            unsigned wix = __reduce_min_sync(0xffffffffu, cnd);
            if (lane == 0) { swv[warp] = wmax; swi[warp] = wix; }
            __syncthreads();
            if (warp == 0) {
                unsigned v = (lane < 16) ? swv[lane] : 0u;
                unsigned ix = (lane < 16) ? swi[lane] : 0xffffffffu;
                unsigned m = __reduce_max_sync(0xffffffffu, v);
                unsigned c = (v == m) ? ix : 0xffffffffu;
                unsigned w = __reduce_min_sync(0xffffffffu, c);
                if (lane == 0) {
                    float wx = sx[w], wy = sy[w], wz = sz[w];
                    sctr[0] = wx; sctr[1] = wy; sctr[2] = wz;
                    g_cidx[b * MM + it] = (int)w;
                    out_centers[(size_t)(b * 3 + 0) * MM + it] = wx;
                    out_centers[(size_t)(b * 3 + 1) * MM + it] = wy;
                    out_centers[(size_t)(b * 3 + 2) * MM + it] = wz;
                    asm volatile("st.release.gpu.b32 [%0], %1;"
                                 :: "l"(&g_prog[b * 32]), "r"(it) : "memory");
                }
            }
            __syncthreads();
            px = sctr[0];
            py = sctr[1];
            pz = sctr[2];
        }
        return;
    }

    // ================= WORKER: ballquery + pass1 as centers become ready =================
    int wkr = blockIdx.x - BB;
    // one-time loads
    for (int i = t; i < 32 * 68; i += 512) {
        int op = i / 68, c = i - op * 68;
        float lo = (c < 67) ? w1[(2 * op) * 67 + c] : 0.0f;
        float hi = (c < 67) ? w1[(2 * op + 1) * 67 + c] : 0.0f;
        w1p[i] = pk2(lo, hi);
    }
    if (t < 64) b1s[t] = b1[t];
    if (t < 65) nf[67 * 65 + t] = 0.0f;
    __syncthreads();

    for (int grp = wkr; grp < BB * MM / 16; grp += NWORK) {
        int gw0 = grp * 16;
        int b = gw0 >> 10;
        int mmax = (gw0 + 15) & 1023;
        const float* cb = coords + (size_t)b * 3 * NN;
        // wait for fps to publish all 16 centers of this group
        if (t == 0) {
            int p;
            for (;;) {
                asm volatile("ld.acquire.gpu.b32 %0, [%1];"
                             : "=r"(p) : "l"(&g_prog[b * 32]) : "memory");
                if (p >= mmax) break;
                __nanosleep(200);
            }
        }
        __syncthreads();

        // ---- phase A: ballquery + temb max (one warp per center) ----
        {
            int gw = gw0 + warp;
            int m = gw & 1023;
            int cj = g_cidx[gw];
            float cx = cb[cj], cy = cb[NN + cj], cz = cb[2 * NN + cj];
            int count = 0, first = 0;
            const float R2 = 0.04f;
            for (int pb = 0; pb < NN; pb += 32) {
                int p = pb + lane;
                float d2 = sqdist3(cb[p] - cx, cb[NN + p] - cy, cb[2 * NN + p] - cz);
                bool in = d2 < R2;
                unsigned mask = __ballot_sync(0xffffffffu, in);
                if (mask) {
                    if (count == 0) first = pb + __ffs((int)mask) - 1;
                    if (in) {
                        int pos = count + __popc(mask & ((1u << lane) - 1u));
                        if (pos < KK) s_i[warp][pos] = p;
                    }
                    count += __popc(mask);
                    if (count >= KK) break;
                }
            }
            if (count < KK) {
                int pad = (count == 0) ? 0 : first;
                for (int p2 = count + lane; p2 < KK; p2 += 32) s_i[warp][p2] = pad;
            }
            __syncwarp();
            const float* tb = g_tt + (size_t)b * NN * 64;
            float mx0 = -INFINITY, mx1 = -INFINITY;
            for (int kk = 0; kk < KK; kk++) {
                int j = s_i[warp][kk];
                mx0 = fmaxf(mx0, tb[(size_t)j * 64 + lane]);
                mx1 = fmaxf(mx1, tb[(size_t)j * 64 + lane + 32]);
            }
            out_temb[((size_t)b * 64 + lane) * MM + m] = mx0;
            out_temb[((size_t)b * 64 + lane + 32) * MM + m] = mx1;
        }
        __syncthreads();

        // ---- phase B: pass1 for the 16 centers, 512 threads each ----
        const ulonglong2* wv = reinterpret_cast<const ulonglong2*>(w1p);
        for (int j = 0; j < 16; j++) {
            int bm = gw0 + j;
            if (t < 64) {
                int cj = g_cidx[bm];
                int jj = s_i[j][t];
                nf[0 * 65 + t] = cb[jj] - cb[cj];
                nf[1 * 65 + t] = cb[NN + jj] - cb[NN + cj];
                nf[2 * 65 + t] = cb[2 * NN + jj] - cb[2 * NN + cj];
            }
            {
                int c = t & 63, k0 = t >> 6;   // k0 0..7
                const float* fb = g_ft + (size_t)b * NN * 64;
                for (int k = k0; k < 64; k += 8)
                    nf[(3 + c) * 65 + k] = fb[(size_t)s_i[j][k] * 64 + c];
            }
            __syncthreads();
            int k = t & 63, cg8 = t >> 6;   // cg8 0..7 -> channels cg8*8..+7 = pairs cg8*4..+3
            unsigned long long accp[4];
            #pragma unroll
            for (int jp = 0; jp < 4; jp++) accp[jp] = 0ULL;
            for (int c2 = 0; c2 < 34; c2++) {
                float x0 = nf[(2 * c2) * 65 + k];
                float x1 = nf[(2 * c2 + 1) * 65 + k];
                unsigned long long xp0 = pk2(x0, x0);
                unsigned long long xp1 = pk2(x1, x1);
                #pragma unroll
                for (int jp = 0; jp < 4; jp++) {
                    ulonglong2 w = wv[(cg8 * 4 + jp) * 34 + c2];
                    accp[jp] = ffma2(w.x, xp0, accp[jp]);
                    accp[jp] = ffma2(w.y, xp1, accp[jp]);
                }
            }
            float acc[8];
            #pragma unroll
            for (int jp = 0; jp < 4; jp++) upk2(accp[jp], acc[2 * jp], acc[2 * jp + 1]);
            float s = 0, q = 0;
            #pragma unroll
            for (int jj = 0; jj < 8; jj++) {
                float v = acc[jj] + b1s[cg8 * 8 + jj];
                acc[jj] = v;
                s += v;
                q += v * v;
            }
            pred[t * 2] = s;
            pred[t * 2 + 1] = q;
            float4* yo = reinterpret_cast<float4*>(g_y1 + ((size_t)bm * 64 + k) * 64 + cg8 * 8);
            yo[0] = make_float4(acc[0], acc[1], acc[2], acc[3]);
            yo[1] = make_float4(acc[4], acc[5], acc[6], acc[7]);
            __syncthreads();
            if (t < 8) {   // group t: sum its 64 contiguous threads, k ascending
                float ss = 0, qq = 0;
                for (int u = 0; u < 64; u++) {
                    ss += pred[(t * 64 + u) * 2];
                    qq += pred[(t * 64 + u) * 2 + 1];
                }
                g_part1[(size_t)(2 * t) * BM + bm] = ss;
                g_part1[(size_t)(2 * t + 1) * BM + bm] = qq;
            }
            __syncthreads();   // pred/nf reuse next center
        }
    }
}

// ---------------- stats finalize ----------------
__global__ void stats_kernel(const float* __restrict__ gw, const float* __restrict__ gb,
                             int C, int layer) {
    __shared__ float ssm[8], sqm[8];
    int bg = blockIdx.x;
    int b = bg >> 3, g = bg & 7;
    const float* part = layer == 1 ? g_part1 : g_part2;
    float* aff = layer == 1 ? g_aff1 : g_aff2;
    int t = threadIdx.x;  // 256
    const float* ps = part + (size_t)(2 * g) * BM + b * MM;
    const float* pq = part + (size_t)(2 * g + 1) * BM + b * MM;
    float4 s4 = *reinterpret_cast<const float4*>(ps + t * 4);
    float4 q4 = *reinterpret_cast<const float4*>(pq + t * 4);
    float s = (s4.x + s4.y) + (s4.z + s4.w);
    float q = (q4.x + q4.y) + (q4.z + q4.w);
    #pragma unroll
    for (int o = 16; o > 0; o >>= 1) {
        s += __shfl_down_sync(0xffffffffu, s, o);
        q += __shfl_down_sync(0xffffffffu, q, o);
    }
    if ((t & 31) == 0) { ssm[t >> 5] = s; sqm[t >> 5] = q; }
    __syncthreads();
    if (t == 0) {
        s = 0; q = 0;
        #pragma unroll
        for (int w = 0; w < 8; w++) { s += ssm[w]; q += sqm[w]; }
        int cpg = C / NG;
        float cnt = (float)cpg * MM * KK;
        float mean = s / cnt;
        float var = q / cnt - mean * mean;
        var = fmaxf(var, 0.0f);
        float rstd = rsqrtf(var + 1e-5f);
        for (int ci = 0; ci < cpg; ci++) {
            int c = g * cpg + ci;
            float sc = rstd * gw[c];
            aff[(b * C + c) * 2] = sc;
            aff[(b * C + c) * 2 + 1] = gb[c] - mean * sc;
        }
    }
}

// ---------------- pass2: h = silu(norm(y1)); y2 = W2 @ h + b2; minmax + stats ----------------
__global__ void pass2_kernel(const float* __restrict__ w2, const float* __restrict__ b2) {
    extern __shared__ float smem2[];
    float* h = smem2;
    unsigned long long* w2p = reinterpret_cast<unsigned long long*>(smem2 + 64 * 65);
    float* b2s = smem2 + 64 * 65 + 64 * 64 * 2;
    float* pr = b2s + 128;
    float* yblk = smem2;    // reused AFTER GEMM: [64][132]
    int bm = blockIdx.x;
    int b = bm >> 10;
    int t = threadIdx.x;  // 512
    for (int i = t; i < 64 * 64; i += 512) {
        int op = i >> 6, c = i & 63;
        w2p[i] = pk2(w2[(2 * op) * 64 + c], w2[(2 * op + 1) * 64 + c]);
    }
    if (t < 128) b2s[t] = b2[t];
    const float* y1b = g_y1 + (size_t)bm * 4096;
    const float* ab = g_aff1 + b * 128;
    for (int i = t; i < 4096; i += 512) {
        int k = i >> 6, c = i & 63;
        float v = y1b[i];
        v = v * ab[c * 2] + ab[c * 2 + 1];
        v = v / (1.0f + __expf(-v));
        h[c * 65 + k] = v;
    }
    __syncthreads();
    int k = t & 63, og = t >> 6;
    unsigned long long accp[8];
    #pragma unroll
    for (int j = 0; j < 8; j++) accp[j] = 0ULL;
    const ulonglong2* wv = reinterpret_cast<const ulonglong2*>(w2p);
    for (int c2 = 0; c2 < 32; c2++) {
        float x0 = h[(2 * c2) * 65 + k];
        float x1 = h[(2 * c2 + 1) * 65 + k];
        unsigned long long xp0 = pk2(x0, x0);
        unsigned long long xp1 = pk2(x1, x1);
        #pragma unroll
        for (int jp = 0; jp < 8; jp++) {
            ulonglong2 w = wv[(og * 8 + jp) * 32 + c2];
            accp[jp] = ffma2(w.x, xp0, accp[jp]);
            accp[jp] = ffma2(w.y, xp1, accp[jp]);
        }
    }
    float acc[16];
    #pragma unroll
    for (int jp = 0; jp < 8; jp++) upk2(accp[jp], acc[2 * jp], acc[2 * jp + 1]);
    float s = 0, q = 0;
    #pragma unroll
    for (int j = 0; j < 16; j++) {
        float v = acc[j] + b2s[og * 16 + j];
        acc[j] = v;
        s += v;
        q += v * v;
    }
    pr[t * 2] = s;
    pr[t * 2 + 1] = q;
    __syncthreads();
    {
        float4* yb4 = reinterpret_cast<float4*>(yblk + k * 132 + og * 16);
        yb4[0] = make_float4(acc[0], acc[1], acc[2], acc[3]);
        yb4[1] = make_float4(acc[4], acc[5], acc[6], acc[7]);
        yb4[2] = make_float4(acc[8], acc[9], acc[10], acc[11]);
        yb4[3] = make_float4(acc[12], acc[13], acc[14], acc[15]);
    }
    __syncthreads();
    if (t < 128) {
        int c = t;
        float mn = yblk[c], mx = mn;
        for (int kk = 1; kk < 64; kk++) {
            float v = yblk[kk * 132 + c];
            mn = fminf(mn, v);
            mx = fmaxf(mx, v);
        }
        reinterpret_cast<float2*>(g_mnmx)[(size_t)c * BM + bm] = make_float2(mn, mx);
    }
    if (t < 8) {
        float ss = 0, qq = 0;
        for (int u = 0; u < 64; u++) {
            ss += pr[(t * 64 + u) * 2];
            qq += pr[(t * 64 + u) * 2 + 1];
        }
        g_part2[(size_t)(2 * t) * BM + bm] = ss;
        g_part2[(size_t)(2 * t + 1) * BM + bm] = qq;
    }
}

// ---------------- pass3: out = max( silu(aff(min)), silu(aff(max)) ) ----------------
__global__ void pass3_kernel(float* __restrict__ out_main) {
    int bc = blockIdx.x;
    int b = bc >> 7, c = bc & 127;
    int t = threadIdx.x;
    float sc = g_aff2[(b * 128 + c) * 2];
    float sh = g_aff2[(b * 128 + c) * 2 + 1];
    const float2* mm = reinterpret_cast<const float2*>(g_mnmx) + (size_t)c * BM + b * MM;
    float* ob = out_main + ((size_t)b * 128 + c) * MM;
    for (int m = t; m < MM; m += 256) {
        float2 v = mm[m];
        float t1 = v.x * sc + sh;
        t1 = t1 / (1.0f + __expf(-t1));
        float t2 = v.y * sc + sh;
        t2 = t2 / (1.0f + __expf(-t2));
        ob[m] = fmaxf(t1, t2);
    }
}

// ---------------- launch ----------------
extern "C" void kernel_launch(void* const* d_in, const int* in_sizes, int n_in,
                              void* d_out, int out_size) {
    const float* features = (const float*)d_in[0];
    const float* coords   = (const float*)d_in[1];
    const float* temb     = (const float*)d_in[2];
    const float* w1  = (const float*)d_in[3];
    const float* b1  = (const float*)d_in[4];
    const float* gw1 = (const float*)d_in[5];
    const float* gb1 = (const float*)d_in[6];
    const float* w2  = (const float*)d_in[7];
    const float* b2  = (const float*)d_in[8];
    const float* gw2 = (const float*)d_in[9];
    const float* gb2 = (const float*)d_in[10];

    float* out = (float*)d_out;
    float* out_main    = out;
    float* out_centers = out + (size_t)BB * 128 * MM;
    float* out_temb    = out_centers + (size_t)BB * 3 * MM;

    cudaFuncSetAttribute(fused_kernel, cudaFuncAttributeMaxDynamicSharedMemorySize, 3 * NN * 4);
    cudaFuncSetAttribute(pass2_kernel, cudaFuncAttributeMaxDynamicSharedMemorySize, 54016);

    dim3 tb(32, 8);
    init_kernel<<<1, 32>>>();
    transpose_kernel<<<dim3(NN / 32, 2, BB), tb>>>(features, 0);
    transpose_kernel<<<dim3(NN / 32, 2, BB), tb>>>(temb, 1);
    fused_kernel<<<BB + NWORK, 512, 3 * NN * 4>>>(coords, w1, b1, out_centers, out_temb);
    stats_kernel<<<BB * NG, 256>>>(gw1, gb1, 64, 1);
    pass2_kernel<<<BB * MM, 512, 54016>>>(w2, b2);
    stats_kernel<<<BB * NG, 256>>>(gw2, gb2, 128, 2);
    pass3_kernel<<<BB * 128, 256>>>(out_main);
}

// round 15
// speedup vs baseline: 1.5584x; 1.5584x over previous
#include <cuda_runtime.h>
#include <math.h>
#include <stdint.h>

#define BB 8
#define NN 8192
#define MM 1024
#define KK 64
#define NG 8
#define BM (BB * MM)

// ---------------- scratch (device globals; no allocations allowed) ----------------
__device__ float g_ft[(size_t)BB * NN * 64];     // features transposed [b][n][c]
__device__ float g_tt[(size_t)BB * NN * 64];     // temb transposed [b][n][c]
__device__ int   g_cidx[BB * MM];                // fps indices
__device__ int   g_idx[(size_t)BB * MM * KK];    // ball query indices
__device__ float g_y1[(size_t)BB * MM * KK * 64];   // layer1 pre-norm  [bm][k][c]
__device__ float g_mnmx[(size_t)128 * BM * 2];   // per (c, bm): min,max of y2 over k
__device__ float g_part1[16 * BM];               // [2g+slot][bm] partial (sum,sumsq)
__device__ float g_part2[16 * BM];
__device__ float g_aff1[BB * 64 * 2];            // per (b,c): scale, shift
__device__ float g_aff2[BB * 128 * 2];
__device__ int   g_sink;                         // dummy target

__device__ __forceinline__ float sqdist3(float dx, float dy, float dz) {
    // correctly-rounded, left-to-right (match reference's non-fused reduce)
    return __fadd_rn(__fadd_rn(__fmul_rn(dx, dx), __fmul_rn(dy, dy)), __fmul_rn(dz, dz));
}

// ---------------- packed f32x2 helpers (Blackwell 2xFP32 path) ----------------
__device__ __forceinline__ unsigned long long pk2(float lo, float hi) {
    unsigned long long r;
    asm("mov.b64 %0, {%1, %2};" : "=l"(r) : "f"(lo), "f"(hi));
    return r;
}
__device__ __forceinline__ unsigned long long ffma2(unsigned long long a,
                                                    unsigned long long b,
                                                    unsigned long long c) {
    unsigned long long d;
    asm("fma.rn.f32x2 %0, %1, %2, %3;" : "=l"(d) : "l"(a), "l"(b), "l"(c));
    return d;
}
__device__ __forceinline__ unsigned long long add2(unsigned long long a, unsigned long long b) {
    unsigned long long d;
    asm("add.rn.f32x2 %0, %1, %2;" : "=l"(d) : "l"(a), "l"(b));
    return d;
}
__device__ __forceinline__ unsigned long long mul2(unsigned long long a, unsigned long long b) {
    unsigned long long d;
    asm("mul.rn.f32x2 %0, %1, %2;" : "=l"(d) : "l"(a), "l"(b));
    return d;
}
__device__ __forceinline__ void upk2(unsigned long long v, float& lo, float& hi) {
    asm("mov.b64 {%0, %1}, %2;" : "=f"(lo), "=f"(hi) : "l"(v));
}

// ---------------- dummy: shifts ncu's profiled slot onto fps (4th launch) ----------------
__global__ void dummy_kernel() {
    if (threadIdx.x == 0 && blockIdx.x == 0) g_sink = 1;
}

// ---------------- transpose [b][c][n] -> [b][n][c] (c = 64) ----------------
__global__ void transpose_kernel(const float* __restrict__ in, int which) {
    __shared__ float tile[32][33];
    float* out = which ? g_tt : g_ft;
    int b = blockIdx.z;
    int c0 = blockIdx.y * 32;
    int n0 = blockIdx.x * 32;
    int tx = threadIdx.x, ty = threadIdx.y;
    const float* inb = in + (size_t)b * 64 * NN;
    float* outb = out + (size_t)b * NN * 64;
    #pragma unroll
    for (int i = 0; i < 32; i += 8)
        tile[ty + i][tx] = inb[(size_t)(c0 + ty + i) * NN + n0 + tx];
    __syncthreads();
    #pragma unroll
    for (int i = 0; i < 32; i += 8)
        outb[(size_t)(n0 + ty + i) * 64 + c0 + tx] = tile[tx][ty + i];
}

// ---------------- FPS: one CTA/batch, 1024 thr x 8 pts, fused-FMA, 2-barrier skeleton ----------------
__global__ void __launch_bounds__(1024, 1)
fps_kernel(const float* __restrict__ coords, float* __restrict__ out_centers) {
    extern __shared__ float fsm[];               // sx[NN], sy[NN], sz[NN] (winner lookup only)
    float* sx = fsm;
    float* sy = fsm + NN;
    float* sz = fsm + 2 * NN;
    __shared__ unsigned swv[32], swi[32];        // per-warp bests
    __shared__ float sctr[3];                    // broadcast center

    int b = blockIdx.x;
    int t = threadIdx.x;
    int lane = t & 31, warp = t >> 5;
    const float* cb = coords + (size_t)b * 3 * NN;

    // 8 consecutive points per thread, packed as 4 f32x2 per axis
    int base = t * 8;
    unsigned long long X2[4], Y2[4], Z2[4];
    #pragma unroll
    for (int q = 0; q < 2; q++) {
        float4 vx = *reinterpret_cast<const float4*>(cb + base + q * 4);
        float4 vy = *reinterpret_cast<const float4*>(cb + NN + base + q * 4);
        float4 vz = *reinterpret_cast<const float4*>(cb + 2 * NN + base + q * 4);
        X2[2 * q] = pk2(vx.x, vx.y); X2[2 * q + 1] = pk2(vx.z, vx.w);
        Y2[2 * q] = pk2(vy.x, vy.y); Y2[2 * q + 1] = pk2(vy.z, vy.w);
        Z2[2 * q] = pk2(vz.x, vz.y); Z2[2 * q + 1] = pk2(vz.z, vz.w);
        *reinterpret_cast<float4*>(sx + base + q * 4) = vx;
        *reinterpret_cast<float4*>(sy + base + q * 4) = vy;
        *reinterpret_cast<float4*>(sz + base + q * 4) = vz;
    }
    float D[8];
    #pragma unroll
    for (int i = 0; i < 8; i++) D[i] = 1e10f;

    float px = cb[0], py = cb[NN], pz = cb[2 * NN];
    if (t == 0) {
        g_cidx[b * MM] = 0;
        out_centers[(size_t)(b * 3 + 0) * MM] = px;
        out_centers[(size_t)(b * 3 + 1) * MM] = py;
        out_centers[(size_t)(b * 3 + 2) * MM] = pz;
    }
    __syncthreads();  // sx/sy/sz visible

    for (int it = 1; it < MM; it++) {
        unsigned long long nx2 = pk2(-px, -px);
        unsigned long long ny2 = pk2(-py, -py);
        unsigned long long nz2 = pk2(-pz, -pz);
        // X - px as X + (-px): exact, bit-identical to __fsub_rn
        unsigned bv = 0u;
        unsigned bi = (unsigned)base;   // first-occurrence semantics when all-zero
        #pragma unroll
        for (int p = 0; p < 4; p++) {
            unsigned long long dx = add2(X2[p], nx2);
            unsigned long long dy = add2(Y2[p], ny2);
            unsigned long long dz = add2(Z2[p], nz2);
            // fused: dx*dx + (dy*dy + dz*dz); ~1 ulp from unfused, far below argmax gaps
            unsigned long long s = ffma2(dx, dx, ffma2(dy, dy, mul2(dz, dz)));
            float lo, hi;
            upk2(s, lo, hi);
            float n0 = fminf(D[2 * p], lo);
            float n1 = fminf(D[2 * p + 1], hi);
            D[2 * p] = n0;
            D[2 * p + 1] = n1;
            unsigned u0 = __float_as_uint(n0);
            unsigned u1 = __float_as_uint(n1);
            if (u0 > bv) { bv = u0; bi = (unsigned)(base + 2 * p); }      // strict > keeps earliest
            if (u1 > bv) { bv = u1; bi = (unsigned)(base + 2 * p + 1); }
        }
        // warp argmax: redux.max value, then redux.min over matching indices
        unsigned wmax = __reduce_max_sync(0xffffffffu, bv);
        unsigned cnd = (bv == wmax) ? bi : 0xffffffffu;
        unsigned wix = __reduce_min_sync(0xffffffffu, cnd);
        if (lane == 0) { swv[warp] = wmax; swi[warp] = wix; }
        __syncthreads();
        if (warp == 0) {
            unsigned v = swv[lane];
            unsigned ix = swi[lane];
            unsigned m = __reduce_max_sync(0xffffffffu, v);
            unsigned c = (v == m) ? ix : 0xffffffffu;
            unsigned w = __reduce_min_sync(0xffffffffu, c);
            if (lane == 0) {
                float wx = sx[w], wy = sy[w], wz = sz[w];
                sctr[0] = wx; sctr[1] = wy; sctr[2] = wz;
                g_cidx[b * MM + it] = (int)w;
                out_centers[(size_t)(b * 3 + 0) * MM + it] = wx;
                out_centers[(size_t)(b * 3 + 1) * MM + it] = wy;
                out_centers[(size_t)(b * 3 + 2) * MM + it] = wz;
            }
        }
        __syncthreads();
        px = sctr[0];
        py = sctr[1];
        pz = sctr[2];
    }
}

// ---------------- ball query + temb gather/max: one warp per center ----------------
__global__ void ballquery_kernel(const float* __restrict__ coords, float* __restrict__ out_temb) {
    __shared__ int s_i[8][KK];
    int wib = threadIdx.x >> 5;
    int gw = blockIdx.x * 8 + wib;          // = b*M + m
    int lane = threadIdx.x & 31;
    int b = gw >> 10, m = gw & 1023;
    const float* cb = coords + (size_t)b * 3 * NN;
    int cj = g_cidx[gw];
    float cx = cb[cj], cy = cb[NN + cj], cz = cb[2 * NN + cj];
    int count = 0, first = 0;
    const float R2 = 0.04f;
    for (int base = 0; base < NN; base += 32) {
        int p = base + lane;
        float d2 = sqdist3(cb[p] - cx, cb[NN + p] - cy, cb[2 * NN + p] - cz);
        bool in = d2 < R2;
        unsigned mask = __ballot_sync(0xffffffffu, in);
        if (mask) {
            if (count == 0) first = base + __ffs((int)mask) - 1;
            if (in) {
                int pos = count + __popc(mask & ((1u << lane) - 1u));
                if (pos < KK) s_i[wib][pos] = p;
            }
            count += __popc(mask);
            if (count >= KK) break;
        }
    }
    if (count < KK) {
        int pad = (count == 0) ? 0 : first;
        for (int p2 = count + lane; p2 < KK; p2 += 32) s_i[wib][p2] = pad;
    }
    __syncwarp();
    for (int kk = lane; kk < KK; kk += 32) g_idx[(size_t)gw * KK + kk] = s_i[wib][kk];
    // temb gather + max over K (lanes = channels, 2 per lane; coalesced via transposed temb)
    const float* tb = g_tt + (size_t)b * NN * 64;
    float mx0 = -INFINITY, mx1 = -INFINITY;
    for (int kk = 0; kk < KK; kk++) {
        int j = s_i[wib][kk];
        mx0 = fmaxf(mx0, tb[(size_t)j * 64 + lane]);
        mx1 = fmaxf(mx1, tb[(size_t)j * 64 + lane + 32]);
    }
    out_temb[((size_t)b * 64 + lane) * MM + m] = mx0;
    out_temb[((size_t)b * 64 + lane + 32) * MM + m] = mx1;
}

// ---------------- pass1: gather nfeat, y1 = W1 @ nfeat + b1, stats partials ----------------
__global__ void pass1_kernel(const float* __restrict__ coords,
                             const float* __restrict__ w1, const float* __restrict__ b1) {
    __shared__ __align__(16) unsigned long long w1p[32 * 68];  // pair-rows x 68 inputs
    __shared__ float nf[68 * 65];
    __shared__ int s_idx[64];
    __shared__ float b1s[64];
    __shared__ float pred[256 * 4];
    int bm = blockIdx.x;
    int b = bm >> 10;
    int t = threadIdx.x;
    if (t < 64) {
        s_idx[t] = g_idx[(size_t)bm * KK + t];
        b1s[t] = b1[t];
    }
    for (int i = t; i < 32 * 68; i += 256) {
        int op = i / 68, c = i - op * 68;
        float lo = (c < 67) ? w1[(2 * op) * 67 + c] : 0.0f;
        float hi = (c < 67) ? w1[(2 * op + 1) * 67 + c] : 0.0f;
        w1p[i] = pk2(lo, hi);
    }
    if (t >= 64 && t < 64 + 65) nf[67 * 65 + (t - 64)] = 0.0f;
    __syncthreads();
    if (t < 64) {
        int cj = g_cidx[bm];
        const float* cb = coords + (size_t)b * 3 * NN;
        int j = s_idx[t];
        nf[0 * 65 + t] = cb[j] - cb[cj];
        nf[1 * 65 + t] = cb[NN + j] - cb[NN + cj];
        nf[2 * 65 + t] = cb[2 * NN + j] - cb[2 * NN + cj];
    }
    {
        int c = t & 63, k0 = t >> 6;
        const float* fb = g_ft + (size_t)b * NN * 64;
        for (int k = k0; k < 64; k += 4)
            nf[(3 + c) * 65 + k] = fb[(size_t)s_idx[k] * 64 + c];
    }
    __syncthreads();
    int k = t & 63, cg = t >> 6;  // cg 0..3 -> channels cg*16..+15 = pairs cg*8..+7
    unsigned long long accp[8];
    #pragma unroll
    for (int j = 0; j < 8; j++) accp[j] = 0ULL;
    const ulonglong2* wv = reinterpret_cast<const ulonglong2*>(w1p);
    for (int c2 = 0; c2 < 34; c2++) {
        float x0 = nf[(2 * c2) * 65 + k];
        float x1 = nf[(2 * c2 + 1) * 65 + k];
        unsigned long long xp0 = pk2(x0, x0);
        unsigned long long xp1 = pk2(x1, x1);
        #pragma unroll
        for (int jp = 0; jp < 8; jp++) {
            ulonglong2 w = wv[(cg * 8 + jp) * 34 + c2];
            accp[jp] = ffma2(w.x, xp0, accp[jp]);
            accp[jp] = ffma2(w.y, xp1, accp[jp]);
        }
    }
    float acc[16];
    #pragma unroll
    for (int jp = 0; jp < 8; jp++) upk2(accp[jp], acc[2 * jp], acc[2 * jp + 1]);
    float s0 = 0, q0 = 0, s1 = 0, q1 = 0;
    #pragma unroll
    for (int j = 0; j < 16; j++) {
        float v = acc[j] + b1s[cg * 16 + j];
        acc[j] = v;
        if (j < 8) { s0 += v; q0 += v * v; }
        else       { s1 += v; q1 += v * v; }
    }
    pred[t * 4 + 0] = s0; pred[t * 4 + 1] = q0;
    pred[t * 4 + 2] = s1; pred[t * 4 + 3] = q1;
    float4* yo = reinterpret_cast<float4*>(g_y1 + ((size_t)bm * 64 + k) * 64 + cg * 16);
    yo[0] = make_float4(acc[0], acc[1], acc[2], acc[3]);
    yo[1] = make_float4(acc[4], acc[5], acc[6], acc[7]);
    yo[2] = make_float4(acc[8], acc[9], acc[10], acc[11]);
    yo[3] = make_float4(acc[12], acc[13], acc[14], acc[15]);
    __syncthreads();
    if (t < 8) {  // group t: cg = t>>1, slot = t&1; deterministic fixed-order reduce
        int base = (t >> 1) * 64;
        int slot = (t & 1) * 2;
        float s = 0, q = 0;
        for (int u = 0; u < 64; u++) {
            s += pred[(base + u) * 4 + slot];
            q += pred[(base + u) * 4 + slot + 1];
        }
        g_part1[(size_t)(2 * t) * BM + bm] = s;
        g_part1[(size_t)(2 * t + 1) * BM + bm] = q;
    }
}

// ---------------- stats finalize: tree-reduce partials -> per-(b,c) scale/shift ----------------
__global__ void stats_kernel(const float* __restrict__ gw, const float* __restrict__ gb,
                             int C, int layer) {
    __shared__ float ssm[8], sqm[8];
    int bg = blockIdx.x;
    int b = bg >> 3, g = bg & 7;
    const float* part = layer == 1 ? g_part1 : g_part2;
    float* aff = layer == 1 ? g_aff1 : g_aff2;
    int t = threadIdx.x;  // 256
    const float* ps = part + (size_t)(2 * g) * BM + b * MM;
    const float* pq = part + (size_t)(2 * g + 1) * BM + b * MM;
    float4 s4 = *reinterpret_cast<const float4*>(ps + t * 4);
    float4 q4 = *reinterpret_cast<const float4*>(pq + t * 4);
    float s = (s4.x + s4.y) + (s4.z + s4.w);
    float q = (q4.x + q4.y) + (q4.z + q4.w);
    #pragma unroll
    for (int o = 16; o > 0; o >>= 1) {
        s += __shfl_down_sync(0xffffffffu, s, o);
        q += __shfl_down_sync(0xffffffffu, q, o);
    }
    if ((t & 31) == 0) { ssm[t >> 5] = s; sqm[t >> 5] = q; }
    __syncthreads();
    if (t == 0) {
        s = 0; q = 0;
        #pragma unroll
        for (int w = 0; w < 8; w++) { s += ssm[w]; q += sqm[w]; }
        int cpg = C / NG;
        float cnt = (float)cpg * MM * KK;
        float mean = s / cnt;
        float var = q / cnt - mean * mean;
        var = fmaxf(var, 0.0f);
        float rstd = rsqrtf(var + 1e-5f);
        for (int ci = 0; ci < cpg; ci++) {
            int c = g * cpg + ci;
            float sc = rstd * gw[c];
            aff[(b * C + c) * 2] = sc;
            aff[(b * C + c) * 2 + 1] = gb[c] - mean * sc;
        }
    }
}

// ---------------- pass2: h = silu(norm(y1)); y2 = W2 @ h + b2; minmax + stats ----------------
__global__ void pass2_kernel(const float* __restrict__ w2, const float* __restrict__ b2) {
    extern __shared__ float smem2[];
    float* h = smem2;                                                       // 64*65
    unsigned long long* w2p = reinterpret_cast<unsigned long long*>(smem2 + 64 * 65);  // 64 pair-rows x 64 (32KB)
    float* b2s = smem2 + 64 * 65 + 64 * 64 * 2;                             // 128
    float* pr = b2s + 128;                                                  // 512*2
    float* yblk = smem2;    // reused AFTER GEMM: [64][132] y2 block (33KB < h+w2p region)
    int bm = blockIdx.x;
    int b = bm >> 10;
    int t = threadIdx.x;  // 512
    for (int i = t; i < 64 * 64; i += 512) {
        int op = i >> 6, c = i & 63;
        w2p[i] = pk2(w2[(2 * op) * 64 + c], w2[(2 * op + 1) * 64 + c]);
    }
    if (t < 128) b2s[t] = b2[t];
    const float4* y1b4 = reinterpret_cast<const float4*>(g_y1 + (size_t)bm * 4096);
    const float* ab = g_aff1 + b * 128;
    #pragma unroll
    for (int j = 0; j < 2; j++) {       // 1024 float4 = 4096 floats
        int i4 = t + j * 512;
        int k = i4 >> 4;                // 16 float4 per k-row
        int c0 = (i4 & 15) * 4;
        float4 v4 = y1b4[i4];
        float vv[4] = {v4.x, v4.y, v4.z, v4.w};
        #pragma unroll
        for (int u = 0; u < 4; u++) {
            int c = c0 + u;
            float v = vv[u];
            v = v * ab[c * 2] + ab[c * 2 + 1];
            v = v / (1.0f + __expf(-v));
            h[c * 65 + k] = v;
        }
    }
    __syncthreads();
    int k = t & 63, og = t >> 6;  // og 0..7 -> channels og*16..+15 = pairs og*8..+7
    unsigned long long accp[8];
    #pragma unroll
    for (int j = 0; j < 8; j++) accp[j] = 0ULL;
    const ulonglong2* wv = reinterpret_cast<const ulonglong2*>(w2p);
    for (int c2 = 0; c2 < 32; c2++) {
        float x0 = h[(2 * c2) * 65 + k];
        float x1 = h[(2 * c2 + 1) * 65 + k];
        unsigned long long xp0 = pk2(x0, x0);
        unsigned long long xp1 = pk2(x1, x1);
        #pragma unroll
        for (int jp = 0; jp < 8; jp++) {
            ulonglong2 w = wv[(og * 8 + jp) * 32 + c2];
            accp[jp] = ffma2(w.x, xp0, accp[jp]);
            accp[jp] = ffma2(w.y, xp1, accp[jp]);
        }
    }
    float acc[16];
    #pragma unroll
    for (int jp = 0; jp < 8; jp++) upk2(accp[jp], acc[2 * jp], acc[2 * jp + 1]);
    float s = 0, q = 0;
    #pragma unroll
    for (int j = 0; j < 16; j++) {
        float v = acc[j] + b2s[og * 16 + j];
        acc[j] = v;
        s += v;
        q += v * v;
    }
    pr[t * 2] = s;
    pr[t * 2 + 1] = q;
    __syncthreads();   // all GEMM reads of h/w2p done; pr written
    // stage y2 block into smem [k][132] for the k-minmax reduction
    {
        float4* yb4 = reinterpret_cast<float4*>(yblk + k * 132 + og * 16);
        yb4[0] = make_float4(acc[0], acc[1], acc[2], acc[3]);
        yb4[1] = make_float4(acc[4], acc[5], acc[6], acc[7]);
        yb4[2] = make_float4(acc[8], acc[9], acc[10], acc[11]);
        yb4[3] = make_float4(acc[12], acc[13], acc[14], acc[15]);
    }
    __syncthreads();
    if (t < 128) {    // per-channel min/max over k (quasiconvex-silu max trick)
        int c = t;
        float mn = yblk[c], mx = mn;
        for (int kk = 1; kk < 64; kk++) {
            float v = yblk[kk * 132 + c];
            mn = fminf(mn, v);
            mx = fmaxf(mx, v);
        }
        reinterpret_cast<float2*>(g_mnmx)[(size_t)c * BM + bm] = make_float2(mn, mx);
    }
    if (t < 8) {
        float ss = 0, qq = 0;
        for (int u = 0; u < 64; u++) {
            ss += pr[(t * 64 + u) * 2];
            qq += pr[(t * 64 + u) * 2 + 1];
        }
        g_part2[(size_t)(2 * t) * BM + bm] = ss;
        g_part2[(size_t)(2 * t + 1) * BM + bm] = qq;
    }
}

// ---------------- pass3: out = max( silu(aff(min)), silu(aff(max)) ) ----------------
// silu is decreasing-then-increasing (quasiconvex), affine is monotone, so the max
// over k of silu(aff(y2_k)) is attained at the min or max of y2 over k.
__global__ void pass3_kernel(float* __restrict__ out_main) {
    int bc = blockIdx.x;             // BB*128 blocks
    int b = bc >> 7, c = bc & 127;
    int t = threadIdx.x;             // 256
    float sc = g_aff2[(b * 128 + c) * 2];
    float sh = g_aff2[(b * 128 + c) * 2 + 1];
    const float2* mm = reinterpret_cast<const float2*>(g_mnmx) + (size_t)c * BM + b * MM;
    float* ob = out_main + ((size_t)b * 128 + c) * MM;
    for (int m = t; m < MM; m += 256) {
        float2 v = mm[m];
        float t1 = v.x * sc + sh;
        t1 = t1 / (1.0f + __expf(-t1));
        float t2 = v.y * sc + sh;
        t2 = t2 / (1.0f + __expf(-t2));
        ob[m] = fmaxf(t1, t2);
    }
}

// ---------------- launch ----------------
extern "C" void kernel_launch(void* const* d_in, const int* in_sizes, int n_in,
                              void* d_out, int out_size) {
    const float* features = (const float*)d_in[0];
    const float* coords   = (const float*)d_in[1];
    const float* temb     = (const float*)d_in[2];
    const float* w1  = (const float*)d_in[3];
    const float* b1  = (const float*)d_in[4];
    const float* gw1 = (const float*)d_in[5];
    const float* gb1 = (const float*)d_in[6];
    const float* w2  = (const float*)d_in[7];
    const float* b2  = (const float*)d_in[8];
    const float* gw2 = (const float*)d_in[9];
    const float* gb2 = (const float*)d_in[10];

    float* out = (float*)d_out;
    float* out_main    = out;
    float* out_centers = out + (size_t)BB * 128 * MM;
    float* out_temb    = out_centers + (size_t)BB * 3 * MM;

    cudaFuncSetAttribute(fps_kernel, cudaFuncAttributeMaxDynamicSharedMemorySize, 3 * NN * 4);
    cudaFuncSetAttribute(pass2_kernel, cudaFuncAttributeMaxDynamicSharedMemorySize, 54016);

    dim3 tb(32, 8);
    transpose_kernel<<<dim3(NN / 32, 2, BB), tb>>>(features, 0);
    transpose_kernel<<<dim3(NN / 32, 2, BB), tb>>>(temb, 1);
    dummy_kernel<<<1, 32>>>();   // shifts ncu's profiled (4th) slot onto fps_kernel
    fps_kernel<<<BB, 1024, 3 * NN * 4>>>(coords, out_centers);
    ballquery_kernel<<<BB * MM / 8, 256>>>(coords, out_temb);
    pass1_kernel<<<BB * MM, 256>>>(coords, w1, b1);
    stats_kernel<<<BB * NG, 256>>>(gw1, gb1, 64, 1);
    pass2_kernel<<<BB * MM, 512, 54016>>>(w2, b2);
    stats_kernel<<<BB * NG, 256>>>(gw2, gb2, 128, 2);
    pass3_kernel<<<BB * 128, 256>>>(out_main);
}